// round 1
// baseline (speedup 1.0000x reference)
#include <cuda_runtime.h>

// Problem constants (fixed shapes)
#define NN 100000
#define EE 1600000
#define DD 128
#define HH 64
#define CC 10
#define GG 1024

// ---------------- scratch (device globals; no allocations allowed) ----------
__device__ __align__(16) float g_bufA[NN * HH];   // xw of current layer
__device__ __align__(16) float g_bufB[NN * HH];   // aggregated output of current layer
__device__ __align__(16) float g_deg [NN];        // degree, then dinv in-place
__device__ __align__(16) float g_pool[GG * HH];
__device__ float g_cnt[GG];
__device__ int   g_is64;                          // 1 if indices are int64, 0 if int32

// ---------------- helpers ----------------------------------------------------
__device__ __forceinline__ int load_idx(const void* p, long long i) {
    // branch on runtime-detected dtype
    if (g_is64) return (int)((const long long*)p)[i];
    return ((const int*)p)[i];
}

__device__ __forceinline__ void red_add_v4(float4* addr, float4 v) {
    asm volatile("red.global.add.v4.f32 [%0], {%1,%2,%3,%4};"
                 :: "l"(addr), "f"(v.x), "f"(v.y), "f"(v.z), "f"(v.w)
                 : "memory");
}

// ---------------- dtype sniffer ----------------------------------------------
// If edge_index is int64 (little-endian, values in [0, N)), every odd 32-bit
// word is 0. If int32, odd words are random node ids (P(all zero) ~ 0).
__global__ void k_detect(const unsigned int* w) {
    __shared__ unsigned int s[256];
    unsigned int acc = 0;
    // sample 256*64 = 16384 pairs spread over the first EE index pairs
    const int stride = EE / (256 * 64);   // 97
    for (int j = 0; j < 64; ++j) {
        long long pair = (long long)(threadIdx.x * 64 + j) * stride;
        acc |= w[2 * pair + 1];
    }
    s[threadIdx.x] = acc;
    __syncthreads();
    for (int st = 128; st > 0; st >>= 1) {
        if (threadIdx.x < st) s[threadIdx.x] |= s[threadIdx.x + st];
        __syncthreads();
    }
    if (threadIdx.x == 0) g_is64 = (s[0] == 0u) ? 1 : 0;
}

// ---------------- degree / dinv ------------------------------------------------
__global__ void k_deg_init() {
    int i = blockIdx.x * blockDim.x + threadIdx.x;
    if (i < NN) g_deg[i] = 1.0f;   // self loop
}

__global__ void k_deg_count(const void* ei) {
    int e = blockIdx.x * blockDim.x + threadIdx.x;
    if (e < EE) {
        int c = load_idx(ei, (long long)EE + e);   // col = edge_index[1]
        atomicAdd(&g_deg[c], 1.0f);
    }
}

__global__ void k_dinv() {
    int i = blockIdx.x * blockDim.x + threadIdx.x;
    if (i < NN) g_deg[i] = rsqrtf(g_deg[i]);   // deg >= 1 always
}

// ---------------- tiled fp32 GEMM: Y(N,64) = X(N,K) @ W(K,64) ------------------
// block = 256 threads, 64-row tile, K tiled by 64. Writes g_bufA.
template <int K, bool EXT>
__global__ void k_gemm(const float* __restrict__ Xext, const float* __restrict__ W) {
    __shared__ float sW[64 * 64];
    __shared__ float sX[64 * 65];   // +1 pad: kills the stride-64 bank conflict

    const float* __restrict__ X = EXT ? Xext : (const float*)g_bufB;
    float* __restrict__ Y = g_bufA;

    const int tid  = threadIdx.x;
    const int row0 = blockIdx.x * 64;
    const int rg   = tid >> 4;          // 0..15 (row group of 4)
    const int c0   = (tid & 15) * 4;    // 0..60 (4 output cols)

    float4 acc[4];
#pragma unroll
    for (int i = 0; i < 4; ++i) acc[i] = make_float4(0.f, 0.f, 0.f, 0.f);

    for (int kt = 0; kt < K; kt += 64) {
#pragma unroll
        for (int j = 0; j < 16; ++j) {
            int idx = j * 256 + tid;                 // 0..4095
            sW[idx] = W[(kt + (idx >> 6)) * HH + (idx & 63)];
        }
#pragma unroll
        for (int j = 0; j < 16; ++j) {
            int idx = j * 256 + tid;
            int r = idx >> 6, kk = idx & 63;
            int grow = row0 + r;
            sX[r * 65 + kk] = (grow < NN) ? X[(long long)grow * K + kt + kk] : 0.0f;
        }
        __syncthreads();

#pragma unroll 8
        for (int kk = 0; kk < 64; ++kk) {
            float4 w = *(const float4*)&sW[kk * 64 + c0];
#pragma unroll
            for (int i = 0; i < 4; ++i) {
                float xv = sX[(rg * 4 + i) * 65 + kk];
                acc[i].x += xv * w.x;
                acc[i].y += xv * w.y;
                acc[i].z += xv * w.z;
                acc[i].w += xv * w.w;
            }
        }
        __syncthreads();
    }

#pragma unroll
    for (int i = 0; i < 4; ++i) {
        int grow = row0 + rg * 4 + i;
        if (grow < NN) *(float4*)&Y[grow * HH + c0] = acc[i];
    }
}

// ---------------- self-loop + bias init: bufB = b + dinv^2 * bufA --------------
__global__ void k_self(const float* __restrict__ bias) {
    int t = blockIdx.x * blockDim.x + threadIdx.x;   // N*16 chunks of float4
    if (t >= NN * 16) return;
    int i = t >> 4, c = t & 15;
    float d = g_deg[i];
    float s = d * d;
    float4 v = ((const float4*)g_bufA)[t];
    float4 b = ((const float4*)bias)[c];
    float4 o;
    o.x = b.x + v.x * s;
    o.y = b.y + v.y * s;
    o.z = b.z + v.z * s;
    o.w = b.w + v.w * s;
    ((float4*)g_bufB)[t] = o;
}

// ---------------- edge scatter: bufB[col] += norm * bufA[row] ------------------
// 16 threads (lanes) per edge, one float4 each. Index/norm loaded once per edge
// group and shuffled to the other 15 lanes.
__global__ void k_scatter(const void* __restrict__ ei) {
    int t = blockIdx.x * blockDim.x + threadIdx.x;   // EE*16 = 25.6M (exact)
    int e = t >> 4;
    int c = t & 15;
    int lane = threadIdx.x & 31;
    int base = lane & ~15;

    int r = 0, cl = 0;
    float norm = 0.f;
    if ((lane & 15) == 0) {
        r  = load_idx(ei, e);
        cl = load_idx(ei, (long long)EE + e);
        norm = g_deg[r] * g_deg[cl];
    }
    r    = __shfl_sync(0xffffffffu, r, base);
    cl   = __shfl_sync(0xffffffffu, cl, base);
    norm = __shfl_sync(0xffffffffu, norm, base);

    float4 v = ((const float4*)g_bufA)[r * 16 + c];
    v.x *= norm; v.y *= norm; v.z *= norm; v.w *= norm;
    red_add_v4(((float4*)g_bufB) + (cl * 16 + c), v);
}

// ---------------- pooling -------------------------------------------------------
__global__ void k_pool_zero() {
    int t = blockIdx.x * blockDim.x + threadIdx.x;
    if (t < GG * HH) g_pool[t] = 0.0f;
    if (t < GG) g_cnt[t] = 0.0f;
}

__global__ void k_pool(const void* __restrict__ batch) {
    int t = blockIdx.x * blockDim.x + threadIdx.x;   // NN*16 = 1.6M (exact)
    if (t >= NN * 16) return;
    int i = t >> 4, c = t & 15;
    int lane = threadIdx.x & 31;
    int base = lane & ~15;

    int b = 0;
    if ((lane & 15) == 0) b = load_idx(batch, i);
    b = __shfl_sync(0xffffffffu, b, base);

    float4 v = ((const float4*)g_bufB)[t];
    red_add_v4((float4*)&g_pool[b * HH + c * 4], v);
    if (c == 0) atomicAdd(&g_cnt[b], 1.0f);
}

// ---------------- head: out(G,C) = (pool/cnt) @ Wl + bl -------------------------
__global__ void k_final(const float* __restrict__ Wl, const float* __restrict__ bl,
                        float* __restrict__ out) {
    int t = blockIdx.x * blockDim.x + threadIdx.x;
    if (t >= GG * CC) return;
    int g = t / CC, c = t % CC;
    float inv = 1.0f / fmaxf(g_cnt[g], 1.0f);
    float dot = 0.0f;
#pragma unroll
    for (int h = 0; h < HH; ++h) dot += g_pool[g * HH + h] * Wl[h * CC + c];
    out[t] = dot * inv + bl[c];
}

// ---------------- launch ---------------------------------------------------------
extern "C" void kernel_launch(void* const* d_in, const int* in_sizes, int n_in,
                              void* d_out, int out_size) {
    const float* x  = (const float*)d_in[0];
    const void*  ei = d_in[1];
    const void*  bt = d_in[2];
    const float* W1 = (const float*)d_in[3];
    const float* b1 = (const float*)d_in[4];
    const float* W2 = (const float*)d_in[5];
    const float* b2 = (const float*)d_in[6];
    const float* W3 = (const float*)d_in[7];
    const float* b3 = (const float*)d_in[8];
    const float* Wl = (const float*)d_in[9];
    const float* bl = (const float*)d_in[10];
    float* out = (float*)d_out;

    const int TPB = 256;
    const int gN    = (NN + TPB - 1) / TPB;       // node-wise
    const int gE    = (EE + TPB - 1) / TPB;       // edge-wise
    const int gNV4  = NN * 16 / TPB;              // 6250 (exact)
    const int gEV4  = EE * 16 / TPB;              // 100000 (exact)
    const int gGemm = (NN + 63) / 64;             // 1563

    // 0) detect index dtype (int32 vs int64)
    k_detect<<<1, 256>>>((const unsigned int*)ei);

    // 1) degrees -> dinv
    k_deg_init <<<gN, TPB>>>();
    k_deg_count<<<gE, TPB>>>(ei);
    k_dinv     <<<gN, TPB>>>();

    // 2) layer 1
    k_gemm<DD, true><<<gGemm, TPB>>>(x, W1);
    k_self   <<<gNV4, TPB>>>(b1);
    k_scatter<<<gEV4, TPB>>>(ei);

    // 3) layer 2
    k_gemm<HH, false><<<gGemm, TPB>>>(nullptr, W2);
    k_self   <<<gNV4, TPB>>>(b2);
    k_scatter<<<gEV4, TPB>>>(ei);

    // 4) layer 3
    k_gemm<HH, false><<<gGemm, TPB>>>(nullptr, W3);
    k_self   <<<gNV4, TPB>>>(b3);
    k_scatter<<<gEV4, TPB>>>(ei);

    // 5) mean pool + linear head
    k_pool_zero<<<(GG * HH + TPB - 1) / TPB, TPB>>>();
    k_pool     <<<gNV4, TPB>>>(bt);
    k_final    <<<(GG * CC + TPB - 1) / TPB, TPB>>>(Wl, bl, out);
}

// round 2
// speedup vs baseline: 1.5555x; 1.5555x over previous
#include <cuda_runtime.h>

// Problem constants (fixed shapes)
#define NN 100000
#define EE 1600000
#define DD 128
#define HH 64
#define CC 10
#define GG 1024
#define SCAN_BLOCKS ((NN + 255) / 256)   // 391

// ---------------- scratch (device globals; no allocations allowed) ----------
__device__ __align__(16) float g_bufA[NN * HH];   // dinv * (X @ W)
__device__ __align__(16) float g_bufB[NN * HH];   // layer output h
__device__ __align__(16) float g_dinv[NN];
__device__ __align__(16) float g_pool[GG * HH];
__device__ float g_cnt[GG];
__device__ int   g_degi[NN];
__device__ int   g_ptr[NN + 1];
__device__ int   g_cursor[NN];
__device__ int   g_bsum[512];
__device__ int   g_csr[EE];
__device__ int   g_is64;                          // 1 if indices are int64

// ---------------- helpers ----------------------------------------------------
__device__ __forceinline__ int load_idx(const void* p, long long i) {
    if (g_is64) return (int)((const long long*)p)[i];
    return ((const int*)p)[i];
}

__device__ __forceinline__ void red_add_v4(float4* addr, float4 v) {
    asm volatile("red.global.add.v4.f32 [%0], {%1,%2,%3,%4};"
                 :: "l"(addr), "f"(v.x), "f"(v.y), "f"(v.z), "f"(v.w)
                 : "memory");
}

// ---------------- dtype sniffer ----------------------------------------------
__global__ void k_detect(const unsigned int* w) {
    __shared__ unsigned int s[256];
    unsigned int acc = 0;
    const int stride = EE / (256 * 64);   // 97
    for (int j = 0; j < 64; ++j) {
        long long pair = (long long)(threadIdx.x * 64 + j) * stride;
        acc |= w[2 * pair + 1];
    }
    s[threadIdx.x] = acc;
    __syncthreads();
    for (int st = 128; st > 0; st >>= 1) {
        if (threadIdx.x < st) s[threadIdx.x] |= s[threadIdx.x + st];
        __syncthreads();
    }
    if (threadIdx.x == 0) g_is64 = (s[0] == 0u) ? 1 : 0;
}

// ---------------- degree histogram + zero-init ---------------------------------
__global__ void k_zero() {
    int i = blockIdx.x * blockDim.x + threadIdx.x;
    if (i < NN) g_degi[i] = 0;
    if (i < GG * HH) g_pool[i] = 0.0f;
    if (i < GG) g_cnt[i] = 0.0f;
}

__global__ void k_deg_count(const void* ei) {
    int e = blockIdx.x * blockDim.x + threadIdx.x;
    if (e < EE) {
        int c = load_idx(ei, (long long)EE + e);   // col
        atomicAdd(&g_degi[c], 1);
    }
}

__global__ void k_dinv() {
    int i = blockIdx.x * blockDim.x + threadIdx.x;
    if (i < NN) g_dinv[i] = rsqrtf((float)(g_degi[i] + 1));  // +1 self loop
}

// ---------------- 3-kernel exclusive scan of g_degi -> g_ptr -------------------
__global__ void k_scan1() {
    __shared__ int s[256];
    int i = blockIdx.x * 256 + threadIdx.x;
    int v = (i < NN) ? g_degi[i] : 0;
    s[threadIdx.x] = v;
    __syncthreads();
    for (int off = 1; off < 256; off <<= 1) {
        int add = (threadIdx.x >= off) ? s[threadIdx.x - off] : 0;
        __syncthreads();
        s[threadIdx.x] += add;
        __syncthreads();
    }
    if (i < NN) g_ptr[i] = s[threadIdx.x] - v;      // exclusive within block
    if (threadIdx.x == 255) g_bsum[blockIdx.x] = s[255];
}

__global__ void k_scan2() {    // 1 block, 512 threads
    __shared__ int s[512];
    int v = (threadIdx.x < SCAN_BLOCKS) ? g_bsum[threadIdx.x] : 0;
    s[threadIdx.x] = v;
    __syncthreads();
    for (int off = 1; off < 512; off <<= 1) {
        int add = (threadIdx.x >= off) ? s[threadIdx.x - off] : 0;
        __syncthreads();
        s[threadIdx.x] += add;
        __syncthreads();
    }
    if (threadIdx.x < SCAN_BLOCKS) g_bsum[threadIdx.x] = s[threadIdx.x] - v;
}

__global__ void k_scan3() {
    int i = blockIdx.x * blockDim.x + threadIdx.x;
    if (i < NN) {
        int p = g_ptr[i] + g_bsum[i >> 8];
        g_ptr[i] = p;
        g_cursor[i] = p;
    }
    if (i == NN) g_ptr[NN] = EE;
}

// ---------------- CSR fill: bucket rows by col ---------------------------------
__global__ void k_fill(const void* __restrict__ ei) {
    int e = blockIdx.x * blockDim.x + threadIdx.x;
    if (e < EE) {
        int r = load_idx(ei, e);
        int c = load_idx(ei, (long long)EE + e);
        int pos = atomicAdd(&g_cursor[c], 1);
        g_csr[pos] = r;
    }
}

// ---------------- tiled fp32 GEMM: bufA = dinv ⊙ (X(N,K) @ W(K,64)) -------------
template <int K, bool EXT>
__global__ void k_gemm(const float* __restrict__ Xext, const float* __restrict__ W) {
    __shared__ float sW[64 * 64];
    __shared__ float sX[64 * 65];   // +1 pad kills stride-64 conflicts

    const float* __restrict__ X = EXT ? Xext : (const float*)g_bufB;
    float* __restrict__ Y = g_bufA;

    const int tid  = threadIdx.x;
    const int row0 = blockIdx.x * 64;
    const int rg   = tid >> 4;          // 0..15 (row group of 4)
    const int c0   = (tid & 15) * 4;    // 0..60 (4 output cols)

    float4 acc[4];
#pragma unroll
    for (int i = 0; i < 4; ++i) acc[i] = make_float4(0.f, 0.f, 0.f, 0.f);

    for (int kt = 0; kt < K; kt += 64) {
#pragma unroll
        for (int j = 0; j < 16; ++j) {
            int idx = j * 256 + tid;
            sW[idx] = W[(kt + (idx >> 6)) * HH + (idx & 63)];
        }
#pragma unroll
        for (int j = 0; j < 16; ++j) {
            int idx = j * 256 + tid;
            int r = idx >> 6, kk = idx & 63;
            int grow = row0 + r;
            sX[r * 65 + kk] = (grow < NN) ? X[(long long)grow * K + kt + kk] : 0.0f;
        }
        __syncthreads();

#pragma unroll 8
        for (int kk = 0; kk < 64; ++kk) {
            float4 w = *(const float4*)&sW[kk * 64 + c0];
#pragma unroll
            for (int i = 0; i < 4; ++i) {
                float xv = sX[(rg * 4 + i) * 65 + kk];
                acc[i].x += xv * w.x;
                acc[i].y += xv * w.y;
                acc[i].z += xv * w.z;
                acc[i].w += xv * w.w;
            }
        }
        __syncthreads();
    }

#pragma unroll
    for (int i = 0; i < 4; ++i) {
        int grow = row0 + rg * 4 + i;
        if (grow < NN) {
            float d = g_dinv[grow];
            acc[i].x *= d; acc[i].y *= d; acc[i].z *= d; acc[i].w *= d;
            *(float4*)&Y[grow * HH + c0] = acc[i];
        }
    }
}

// ---------------- CSR gather: bufB[i] = dinv[i]*(bufA[i] + Σ bufA[nbr]) + b -----
// 16 lanes per node, one float4 channel chunk each.
__global__ void k_gather(const float* __restrict__ bias) {
    int t = blockIdx.x * blockDim.x + threadIdx.x;   // NN*16 exact
    int i = t >> 4;
    int c = t & 15;
    int lane = threadIdx.x & 31;
    int sub  = lane & 15;
    unsigned mask = 0xFFFFu << (lane & 16);

    int start = g_ptr[i];
    int end   = g_ptr[i + 1];

    const float4* __restrict__ A = (const float4*)g_bufA;
    float4 acc = A[i * 16 + c];   // self loop

    for (int p0 = start; p0 < end; p0 += 16) {
        int myj = 0;
        if (p0 + sub < end) myj = g_csr[p0 + sub];
        int cnt = min(16, end - p0);
        if (cnt == 16) {
#pragma unroll
            for (int k = 0; k < 16; ++k) {
                int j = __shfl_sync(mask, myj, k, 16);
                float4 v = A[j * 16 + c];
                acc.x += v.x; acc.y += v.y; acc.z += v.z; acc.w += v.w;
            }
        } else {
            for (int k = 0; k < cnt; ++k) {
                int j = __shfl_sync(mask, myj, k, 16);
                float4 v = A[j * 16 + c];
                acc.x += v.x; acc.y += v.y; acc.z += v.z; acc.w += v.w;
            }
        }
    }

    float d = g_dinv[i];
    float4 b = ((const float4*)bias)[c];
    float4 o;
    o.x = acc.x * d + b.x;
    o.y = acc.y * d + b.y;
    o.z = acc.z * d + b.z;
    o.w = acc.w * d + b.w;
    ((float4*)g_bufB)[i * 16 + c] = o;
}

// ---------------- pooling -------------------------------------------------------
__global__ void k_pool(const void* __restrict__ batch) {
    int t = blockIdx.x * blockDim.x + threadIdx.x;   // NN*16 exact
    int i = t >> 4, c = t & 15;
    int lane = threadIdx.x & 31;
    int base = lane & ~15;

    int b = 0;
    if ((lane & 15) == 0) b = load_idx(batch, i);
    b = __shfl_sync(0xffffffffu, b, base);

    float4 v = ((const float4*)g_bufB)[t];
    red_add_v4((float4*)&g_pool[b * HH + c * 4], v);
    if (c == 0) atomicAdd(&g_cnt[b], 1.0f);
}

// ---------------- head: out(G,C) = (pool/cnt) @ Wl + bl -------------------------
__global__ void k_final(const float* __restrict__ Wl, const float* __restrict__ bl,
                        float* __restrict__ out) {
    int t = blockIdx.x * blockDim.x + threadIdx.x;
    if (t >= GG * CC) return;
    int g = t / CC, c = t % CC;
    float inv = 1.0f / fmaxf(g_cnt[g], 1.0f);
    float dot = 0.0f;
#pragma unroll
    for (int h = 0; h < HH; ++h) dot += g_pool[g * HH + h] * Wl[h * CC + c];
    out[t] = dot * inv + bl[c];
}

// ---------------- launch ---------------------------------------------------------
extern "C" void kernel_launch(void* const* d_in, const int* in_sizes, int n_in,
                              void* d_out, int out_size) {
    const float* x  = (const float*)d_in[0];
    const void*  ei = d_in[1];
    const void*  bt = d_in[2];
    const float* W1 = (const float*)d_in[3];
    const float* b1 = (const float*)d_in[4];
    const float* W2 = (const float*)d_in[5];
    const float* b2 = (const float*)d_in[6];
    const float* W3 = (const float*)d_in[7];
    const float* b3 = (const float*)d_in[8];
    const float* Wl = (const float*)d_in[9];
    const float* bl = (const float*)d_in[10];
    float* out = (float*)d_out;

    const int TPB   = 256;
    const int gN    = (NN + TPB - 1) / TPB;       // 391
    const int gN1   = (NN + 1 + TPB - 1) / TPB;   // covers NN
    const int gE    = (EE + TPB - 1) / TPB;       // 6250
    const int gNV4  = NN * 16 / TPB;              // 6250 exact
    const int gGemm = (NN + 63) / 64;             // 1563

    // 0) detect index dtype
    k_detect<<<1, 256>>>((const unsigned int*)ei);

    // 1) degrees, dinv, CSR build
    k_zero     <<<(GG * HH + TPB - 1) / TPB > gN ? (GG * HH + TPB - 1) / TPB : gN, TPB>>>();
    k_deg_count<<<gE, TPB>>>(ei);
    k_dinv     <<<gN, TPB>>>();
    k_scan1    <<<SCAN_BLOCKS, 256>>>();
    k_scan2    <<<1, 512>>>();
    k_scan3    <<<gN1, TPB>>>();
    k_fill     <<<gE, TPB>>>(ei);

    // 2) layer 1
    k_gemm<DD, true><<<gGemm, TPB>>>(x, W1);
    k_gather<<<gNV4, TPB>>>(b1);

    // 3) layer 2
    k_gemm<HH, false><<<gGemm, TPB>>>(nullptr, W2);
    k_gather<<<gNV4, TPB>>>(b2);

    // 4) layer 3
    k_gemm<HH, false><<<gGemm, TPB>>>(nullptr, W3);
    k_gather<<<gNV4, TPB>>>(b3);

    // 5) mean pool + linear head
    k_pool <<<gNV4, TPB>>>(bt);
    k_final<<<(GG * CC + TPB - 1) / TPB, TPB>>>(Wl, bl, out);
}

// round 3
// speedup vs baseline: 1.7065x; 1.0971x over previous
#include <cuda_runtime.h>
#include <cuda_fp16.h>

// Problem constants (fixed shapes)
#define NN 100000
#define EE 1600000
#define DD 128
#define HH 64
#define CC 10
#define GG 1024
#define SCAN_BLOCKS ((NN + 255) / 256)   // 391

// ---------------- scratch (device globals; no allocations allowed) ----------
__device__ __align__(16) __half g_bufA[NN * HH]; // fp16: dinv * (X @ W)
__device__ __align__(16) float g_bufB[NN * HH];  // fp32 layer output h
__device__ __align__(16) float g_dinv[NN];
__device__ __align__(16) float g_pool[GG * HH];
__device__ float g_cnt[GG];
__device__ int   g_degi[NN];
__device__ int   g_ptr[NN + 1];
__device__ int   g_cursor[NN];
__device__ int   g_bsum[512];
__device__ int   g_csr[EE];
__device__ int   g_is64;                          // 1 if indices are int64

// ---------------- helpers ----------------------------------------------------
__device__ __forceinline__ int load_idx(const void* p, long long i) {
    if (g_is64) return (int)((const long long*)p)[i];
    return ((const int*)p)[i];
}

__device__ __forceinline__ void red_add_v4(float4* addr, float4 v) {
    asm volatile("red.global.add.v4.f32 [%0], {%1,%2,%3,%4};"
                 :: "l"(addr), "f"(v.x), "f"(v.y), "f"(v.z), "f"(v.w)
                 : "memory");
}

// ---------------- dtype sniffer ----------------------------------------------
__global__ void k_detect(const unsigned int* w) {
    __shared__ unsigned int s[256];
    unsigned int acc = 0;
    const int stride = EE / (256 * 64);   // 97
    for (int j = 0; j < 64; ++j) {
        long long pair = (long long)(threadIdx.x * 64 + j) * stride;
        acc |= w[2 * pair + 1];
    }
    s[threadIdx.x] = acc;
    __syncthreads();
    for (int st = 128; st > 0; st >>= 1) {
        if (threadIdx.x < st) s[threadIdx.x] |= s[threadIdx.x + st];
        __syncthreads();
    }
    if (threadIdx.x == 0) g_is64 = (s[0] == 0u) ? 1 : 0;
}

// ---------------- degree histogram + zero-init ---------------------------------
__global__ void k_zero() {
    int i = blockIdx.x * blockDim.x + threadIdx.x;
    if (i < NN) g_degi[i] = 0;
    if (i < GG * HH) g_pool[i] = 0.0f;
    if (i < GG) g_cnt[i] = 0.0f;
}

__global__ void k_deg_count(const void* ei) {
    int e = blockIdx.x * blockDim.x + threadIdx.x;
    if (e < EE) {
        int c = load_idx(ei, (long long)EE + e);   // col
        atomicAdd(&g_degi[c], 1);
    }
}

// ---------------- scan (block-local) + dinv fused ------------------------------
__global__ void k_scan1() {
    __shared__ int s[256];
    int i = blockIdx.x * 256 + threadIdx.x;
    int v = (i < NN) ? g_degi[i] : 0;
    if (i < NN) g_dinv[i] = rsqrtf((float)(v + 1));   // +1 self loop
    s[threadIdx.x] = v;
    __syncthreads();
    for (int off = 1; off < 256; off <<= 1) {
        int add = (threadIdx.x >= off) ? s[threadIdx.x - off] : 0;
        __syncthreads();
        s[threadIdx.x] += add;
        __syncthreads();
    }
    if (i < NN) g_ptr[i] = s[threadIdx.x] - v;      // exclusive within block
    if (threadIdx.x == 255) g_bsum[blockIdx.x] = s[255];
}

__global__ void k_scan2() {    // 1 block, 512 threads
    __shared__ int s[512];
    int v = (threadIdx.x < SCAN_BLOCKS) ? g_bsum[threadIdx.x] : 0;
    s[threadIdx.x] = v;
    __syncthreads();
    for (int off = 1; off < 512; off <<= 1) {
        int add = (threadIdx.x >= off) ? s[threadIdx.x - off] : 0;
        __syncthreads();
        s[threadIdx.x] += add;
        __syncthreads();
    }
    if (threadIdx.x < SCAN_BLOCKS) g_bsum[threadIdx.x] = s[threadIdx.x] - v;
}

__global__ void k_scan3() {
    int i = blockIdx.x * blockDim.x + threadIdx.x;
    if (i < NN) {
        int p = g_ptr[i] + g_bsum[i >> 8];
        g_ptr[i] = p;
        g_cursor[i] = p;
    }
    if (i == 0) g_ptr[NN] = EE;
}

// ---------------- CSR fill: bucket rows by col ---------------------------------
__global__ void k_fill(const void* __restrict__ ei) {
    int e = blockIdx.x * blockDim.x + threadIdx.x;
    if (e < EE) {
        int r = load_idx(ei, e);
        int c = load_idx(ei, (long long)EE + e);
        int pos = atomicAdd(&g_cursor[c], 1);
        g_csr[pos] = r;
    }
}

// ---------------- tiled fp32 GEMM: bufA = fp16(dinv ⊙ (X(N,K) @ W(K,64))) ------
template <int K, bool EXT>
__global__ void k_gemm(const float* __restrict__ Xext, const float* __restrict__ W) {
    __shared__ float sW[64 * 64];
    __shared__ float sX[64 * 65];   // +1 pad kills stride-64 conflicts

    const float* __restrict__ X = EXT ? Xext : (const float*)g_bufB;

    const int tid  = threadIdx.x;
    const int row0 = blockIdx.x * 64;
    const int rg   = tid >> 4;          // 0..15 (row group of 4)
    const int cg   = tid & 15;          // chunk (4 cols)
    const int c0   = cg * 4;

    float4 acc[4];
#pragma unroll
    for (int i = 0; i < 4; ++i) acc[i] = make_float4(0.f, 0.f, 0.f, 0.f);

    for (int kt = 0; kt < K; kt += 64) {
#pragma unroll
        for (int j = 0; j < 16; ++j) {
            int idx = j * 256 + tid;
            sW[idx] = W[(kt + (idx >> 6)) * HH + (idx & 63)];
        }
#pragma unroll
        for (int j = 0; j < 16; ++j) {
            int idx = j * 256 + tid;
            int r = idx >> 6, kk = idx & 63;
            int grow = row0 + r;
            sX[r * 65 + kk] = (grow < NN) ? X[(long long)grow * K + kt + kk] : 0.0f;
        }
        __syncthreads();

#pragma unroll 8
        for (int kk = 0; kk < 64; ++kk) {
            float4 w = *(const float4*)&sW[kk * 64 + c0];
#pragma unroll
            for (int i = 0; i < 4; ++i) {
                float xv = sX[(rg * 4 + i) * 65 + kk];
                acc[i].x += xv * w.x;
                acc[i].y += xv * w.y;
                acc[i].z += xv * w.z;
                acc[i].w += xv * w.w;
            }
        }
        __syncthreads();
    }

#pragma unroll
    for (int i = 0; i < 4; ++i) {
        int grow = row0 + rg * 4 + i;
        if (grow < NN) {
            float d = g_dinv[grow];
            __half2 h0 = __floats2half2_rn(acc[i].x * d, acc[i].y * d);
            __half2 h1 = __floats2half2_rn(acc[i].z * d, acc[i].w * d);
            uint2 u;
            u.x = *(unsigned int*)&h0;
            u.y = *(unsigned int*)&h1;
            ((uint2*)g_bufA)[grow * 16 + cg] = u;   // row = 16 x 8B chunks
        }
    }
}

// ---------------- CSR gather: bufB[i] = dinv[i]*(bufA[i] + Σ bufA[nbr]) + b -----
// 16 lanes per node, one 8B (4-half) channel chunk each.
__device__ __forceinline__ void acc_half4(float4& acc, uint2 u) {
    __half2 h0 = *(__half2*)&u.x;
    __half2 h1 = *(__half2*)&u.y;
    float2 f0 = __half22float2(h0);
    float2 f1 = __half22float2(h1);
    acc.x += f0.x; acc.y += f0.y; acc.z += f1.x; acc.w += f1.y;
}

__global__ void k_gather(const float* __restrict__ bias) {
    int t = blockIdx.x * blockDim.x + threadIdx.x;   // NN*16 exact
    int i = t >> 4;
    int c = t & 15;
    int lane = threadIdx.x & 31;
    int sub  = lane & 15;
    unsigned mask = 0xFFFFu << (lane & 16);

    int start = g_ptr[i];
    int end   = g_ptr[i + 1];

    const uint2* __restrict__ A = (const uint2*)g_bufA;
    float4 acc = make_float4(0.f, 0.f, 0.f, 0.f);
    acc_half4(acc, A[i * 16 + c]);   // self loop

    for (int p0 = start; p0 < end; p0 += 16) {
        int myj = 0;
        if (p0 + sub < end) myj = g_csr[p0 + sub];
        int cnt = min(16, end - p0);
        if (cnt == 16) {
#pragma unroll
            for (int k = 0; k < 16; ++k) {
                int j = __shfl_sync(mask, myj, k, 16);
                acc_half4(acc, A[j * 16 + c]);
            }
        } else {
            for (int k = 0; k < cnt; ++k) {
                int j = __shfl_sync(mask, myj, k, 16);
                acc_half4(acc, A[j * 16 + c]);
            }
        }
    }

    float d = g_dinv[i];
    float4 b = ((const float4*)bias)[c];
    float4 o;
    o.x = acc.x * d + b.x;
    o.y = acc.y * d + b.y;
    o.z = acc.z * d + b.z;
    o.w = acc.w * d + b.w;
    ((float4*)g_bufB)[i * 16 + c] = o;
}

// ---------------- pooling -------------------------------------------------------
__global__ void k_pool(const void* __restrict__ batch) {
    int t = blockIdx.x * blockDim.x + threadIdx.x;   // NN*16 exact
    int i = t >> 4, c = t & 15;
    int lane = threadIdx.x & 31;
    int base = lane & ~15;

    int b = 0;
    if ((lane & 15) == 0) b = load_idx(batch, i);
    b = __shfl_sync(0xffffffffu, b, base);

    float4 v = ((const float4*)g_bufB)[t];
    red_add_v4((float4*)&g_pool[b * HH + c * 4], v);
    if (c == 0) atomicAdd(&g_cnt[b], 1.0f);
}

// ---------------- head: out(G,C) = (pool/cnt) @ Wl + bl -------------------------
__global__ void k_final(const float* __restrict__ Wl, const float* __restrict__ bl,
                        float* __restrict__ out) {
    int t = blockIdx.x * blockDim.x + threadIdx.x;
    if (t >= GG * CC) return;
    int g = t / CC, c = t % CC;
    float inv = 1.0f / fmaxf(g_cnt[g], 1.0f);
    float dot = 0.0f;
#pragma unroll
    for (int h = 0; h < HH; ++h) dot += g_pool[g * HH + h] * Wl[h * CC + c];
    out[t] = dot * inv + bl[c];
}

// ---------------- launch ---------------------------------------------------------
extern "C" void kernel_launch(void* const* d_in, const int* in_sizes, int n_in,
                              void* d_out, int out_size) {
    const float* x  = (const float*)d_in[0];
    const void*  ei = d_in[1];
    const void*  bt = d_in[2];
    const float* W1 = (const float*)d_in[3];
    const float* b1 = (const float*)d_in[4];
    const float* W2 = (const float*)d_in[5];
    const float* b2 = (const float*)d_in[6];
    const float* W3 = (const float*)d_in[7];
    const float* b3 = (const float*)d_in[8];
    const float* Wl = (const float*)d_in[9];
    const float* bl = (const float*)d_in[10];
    float* out = (float*)d_out;

    const int TPB   = 256;
    const int gN    = (NN + TPB - 1) / TPB;       // 391
    const int gE    = (EE + TPB - 1) / TPB;       // 6250
    const int gNV4  = NN * 16 / TPB;              // 6250 exact
    const int gGemm = (NN + 63) / 64;             // 1563
    const int gZero = (GG * HH + TPB - 1) / TPB > gN ? (GG * HH + TPB - 1) / TPB : gN;

    // 0) detect index dtype
    k_detect<<<1, 256>>>((const unsigned int*)ei);

    // 1) degrees, dinv, CSR build
    k_zero     <<<gZero, TPB>>>();
    k_deg_count<<<gE, TPB>>>(ei);
    k_scan1    <<<SCAN_BLOCKS, 256>>>();
    k_scan2    <<<1, 512>>>();
    k_scan3    <<<gN, TPB>>>();
    k_fill     <<<gE, TPB>>>(ei);

    // 2) layer 1
    k_gemm<DD, true><<<gGemm, TPB>>>(x, W1);
    k_gather<<<gNV4, TPB>>>(b1);

    // 3) layer 2
    k_gemm<HH, false><<<gGemm, TPB>>>(nullptr, W2);
    k_gather<<<gNV4, TPB>>>(b2);

    // 4) layer 3
    k_gemm<HH, false><<<gGemm, TPB>>>(nullptr, W3);
    k_gather<<<gNV4, TPB>>>(b3);

    // 5) mean pool + linear head
    k_pool <<<gNV4, TPB>>>(bt);
    k_final<<<(GG * CC + TPB - 1) / TPB, TPB>>>(Wl, bl, out);
}

// round 4
// speedup vs baseline: 2.1719x; 1.2727x over previous
#include <cuda_runtime.h>
#include <cuda_fp16.h>
#include <cstdint>

// Problem constants (fixed shapes)
#define NN 100000
#define EE 1600000
#define DD 128
#define HH 64
#define CC 10
#define GG 1024
#define SCAN_BLOCKS ((NN + 255) / 256)   // 391

// ---------------- scratch (device globals; no allocations allowed) ----------
__device__ __align__(16) __half g_xh  [NN * DD]; // fp16 copy of x
__device__ __align__(16) __half g_bufA[NN * HH]; // fp16: dinv * (X @ W)
__device__ __align__(16) __half g_bufBh[NN * HH];// fp16 layer output (GEMM input)
__device__ __align__(16) float g_bufB[NN * HH];  // fp32 layer-3 output (pool input)
__device__ __align__(16) float g_dinv[NN];
__device__ __align__(16) float g_pool[GG * HH];
__device__ float g_cnt[GG];
__device__ int   g_degi[NN];
__device__ int   g_ptr[NN + 1];
__device__ int   g_cursor[NN];
__device__ int   g_bsum[512];
__device__ int   g_csr[EE];
__device__ int   g_is64;                          // 1 if indices are int64

// ---------------- helpers ----------------------------------------------------
__device__ __forceinline__ int load_idx(const void* p, long long i) {
    if (g_is64) return (int)((const long long*)p)[i];
    return ((const int*)p)[i];
}

__device__ __forceinline__ void red_add_v4(float4* addr, float4 v) {
    asm volatile("red.global.add.v4.f32 [%0], {%1,%2,%3,%4};"
                 :: "l"(addr), "f"(v.x), "f"(v.y), "f"(v.z), "f"(v.w)
                 : "memory");
}

__device__ __forceinline__ void ldsm_x4(uint32_t* r, uint32_t addr) {
    asm volatile("ldmatrix.sync.aligned.m8n8.x4.shared.b16 {%0,%1,%2,%3}, [%4];"
                 : "=r"(r[0]), "=r"(r[1]), "=r"(r[2]), "=r"(r[3]) : "r"(addr));
}

__device__ __forceinline__ void ldsm_x4_t(uint32_t* r, uint32_t addr) {
    asm volatile("ldmatrix.sync.aligned.m8n8.x4.trans.shared.b16 {%0,%1,%2,%3}, [%4];"
                 : "=r"(r[0]), "=r"(r[1]), "=r"(r[2]), "=r"(r[3]) : "r"(addr));
}

__device__ __forceinline__ void mma_16816(float* d, const uint32_t* a, const uint32_t* b) {
    asm volatile("mma.sync.aligned.m16n8k16.row.col.f32.f16.f16.f32 "
                 "{%0,%1,%2,%3}, {%4,%5,%6,%7}, {%8,%9}, {%0,%1,%2,%3};"
                 : "+f"(d[0]), "+f"(d[1]), "+f"(d[2]), "+f"(d[3])
                 : "r"(a[0]), "r"(a[1]), "r"(a[2]), "r"(a[3]), "r"(b[0]), "r"(b[1]));
}

// ---------------- dtype sniffer ----------------------------------------------
__global__ void k_detect(const unsigned int* w) {
    __shared__ unsigned int s[256];
    unsigned int acc = 0;
    const int stride = EE / (256 * 64);   // 97
    for (int j = 0; j < 64; ++j) {
        long long pair = (long long)(threadIdx.x * 64 + j) * stride;
        acc |= w[2 * pair + 1];
    }
    s[threadIdx.x] = acc;
    __syncthreads();
    for (int st = 128; st > 0; st >>= 1) {
        if (threadIdx.x < st) s[threadIdx.x] |= s[threadIdx.x + st];
        __syncthreads();
    }
    if (threadIdx.x == 0) g_is64 = (s[0] == 0u) ? 1 : 0;
}

// ---------------- x fp32 -> fp16 -----------------------------------------------
__global__ void k_cvt(const float* __restrict__ x) {
    int t = blockIdx.x * blockDim.x + threadIdx.x;   // NN*DD/4 exact
    if (t >= NN * DD / 4) return;
    float4 v = ((const float4*)x)[t];
    __half2 h0 = __floats2half2_rn(v.x, v.y);
    __half2 h1 = __floats2half2_rn(v.z, v.w);
    uint2 u;
    u.x = *(unsigned int*)&h0;
    u.y = *(unsigned int*)&h1;
    ((uint2*)g_xh)[t] = u;
}

// ---------------- degree histogram + zero-init ---------------------------------
__global__ void k_zero() {
    int i = blockIdx.x * blockDim.x + threadIdx.x;
    if (i < NN) g_degi[i] = 0;
    if (i < GG * HH) g_pool[i] = 0.0f;
    if (i < GG) g_cnt[i] = 0.0f;
}

__global__ void k_deg_count(const void* ei) {
    int e = blockIdx.x * blockDim.x + threadIdx.x;
    if (e < EE) {
        int c = load_idx(ei, (long long)EE + e);   // col
        atomicAdd(&g_degi[c], 1);
    }
}

// ---------------- scan (block-local) + dinv fused ------------------------------
__global__ void k_scan1() {
    __shared__ int s[256];
    int i = blockIdx.x * 256 + threadIdx.x;
    int v = (i < NN) ? g_degi[i] : 0;
    if (i < NN) g_dinv[i] = rsqrtf((float)(v + 1));   // +1 self loop
    s[threadIdx.x] = v;
    __syncthreads();
    for (int off = 1; off < 256; off <<= 1) {
        int add = (threadIdx.x >= off) ? s[threadIdx.x - off] : 0;
        __syncthreads();
        s[threadIdx.x] += add;
        __syncthreads();
    }
    if (i < NN) g_ptr[i] = s[threadIdx.x] - v;
    if (threadIdx.x == 255) g_bsum[blockIdx.x] = s[255];
}

__global__ void k_scan2() {    // 1 block, 512 threads
    __shared__ int s[512];
    int v = (threadIdx.x < SCAN_BLOCKS) ? g_bsum[threadIdx.x] : 0;
    s[threadIdx.x] = v;
    __syncthreads();
    for (int off = 1; off < 512; off <<= 1) {
        int add = (threadIdx.x >= off) ? s[threadIdx.x - off] : 0;
        __syncthreads();
        s[threadIdx.x] += add;
        __syncthreads();
    }
    if (threadIdx.x < SCAN_BLOCKS) g_bsum[threadIdx.x] = s[threadIdx.x] - v;
}

__global__ void k_scan3() {
    int i = blockIdx.x * blockDim.x + threadIdx.x;
    if (i < NN) {
        int p = g_ptr[i] + g_bsum[i >> 8];
        g_ptr[i] = p;
        g_cursor[i] = p;
    }
    if (i == 0) g_ptr[NN] = EE;
}

// ---------------- CSR fill: bucket rows by col ---------------------------------
__global__ void k_fill(const void* __restrict__ ei) {
    int e = blockIdx.x * blockDim.x + threadIdx.x;
    if (e < EE) {
        int r = load_idx(ei, e);
        int c = load_idx(ei, (long long)EE + e);
        int pos = atomicAdd(&g_cursor[c], 1);
        g_csr[pos] = r;
    }
}

// ---------------- tensor-core GEMM: bufA = fp16(dinv ⊙ (X(N,K) @ W(K,64))) -----
// 256 threads / 8 warps, block tile 128 rows x 64 cols, K chunked by 64.
// fp16 inputs (X fp16 in global, W fp32 converted on smem load), fp32 accum.
template <int K, bool FIRST>
__global__ void k_gemm_tc(const float* __restrict__ W) {
    constexpr int LDX = 72;   // 64 + 8 halfs pad
    __shared__ __half sX[128 * LDX];
    __shared__ __half sW[64 * LDX];

    const __half* __restrict__ X = FIRST ? g_xh : g_bufBh;

    const int tid  = threadIdx.x;
    const int wid  = tid >> 5;
    const int lane = tid & 31;
    const int row0 = blockIdx.x * 128;
    const int wr0  = wid * 16;          // warp row offset within tile

    float acc[8][4];
#pragma unroll
    for (int n = 0; n < 8; ++n)
#pragma unroll
        for (int i = 0; i < 4; ++i) acc[n][i] = 0.0f;

    const uint32_t sX_base = (uint32_t)__cvta_generic_to_shared(sX);
    const uint32_t sW_base = (uint32_t)__cvta_generic_to_shared(sW);

    for (int kt = 0; kt < K; kt += 64) {
        // load X tile: 128 rows x 64 halfs (8 x uint4 per row)
#pragma unroll
        for (int it = 0; it < 4; ++it) {
            int idx = it * 256 + tid;            // 0..1023
            int r = idx >> 3, ch = idx & 7;
            int grow = row0 + r;
            uint4 u = make_uint4(0, 0, 0, 0);
            if (grow < NN) u = *(const uint4*)(X + (long long)grow * K + kt + ch * 8);
            *(uint4*)(sX + r * LDX + ch * 8) = u;
        }
        // load + convert W tile: 64 x 64
#pragma unroll
        for (int it = 0; it < 16; ++it) {
            int idx = it * 256 + tid;            // 0..4095
            int k = idx >> 6, n = idx & 63;
            sW[k * LDX + n] = __float2half(W[(kt + k) * HH + n]);
        }
        __syncthreads();

#pragma unroll
        for (int ks = 0; ks < 64; ks += 16) {
            uint32_t a[4];
            {
                int r = wr0 + (lane & 15);
                int kk = ks + ((lane >> 4) * 8);
                ldsm_x4(a, sX_base + (r * LDX + kk) * 2);
            }
#pragma unroll
            for (int np = 0; np < 4; ++np) {     // n-pairs: (np*16, np*16+8)
                uint32_t b[4];
                int krow = ks + (lane & 7) + (((lane >> 3) & 1) * 8);
                int ncol = np * 16 + ((lane >> 4) * 8);
                ldsm_x4_t(b, sW_base + (krow * LDX + ncol) * 2);
                mma_16816(acc[np * 2 + 0], a, b + 0);
                mma_16816(acc[np * 2 + 1], a, b + 2);
            }
        }
        __syncthreads();
    }

    // epilogue: scale by dinv, store fp16 to g_bufA
    const int rlo = row0 + wr0 + (lane >> 2);
    const int rhi = rlo + 8;
    const int cb  = (lane & 3) * 2;
    float dlo = (rlo < NN) ? g_dinv[rlo] : 0.0f;
    float dhi = (rhi < NN) ? g_dinv[rhi] : 0.0f;
#pragma unroll
    for (int nt = 0; nt < 8; ++nt) {
        int col = nt * 8 + cb;
        if (rlo < NN) {
            __half2 h = __floats2half2_rn(acc[nt][0] * dlo, acc[nt][1] * dlo);
            *(__half2*)(g_bufA + (long long)rlo * HH + col) = h;
        }
        if (rhi < NN) {
            __half2 h = __floats2half2_rn(acc[nt][2] * dhi, acc[nt][3] * dhi);
            *(__half2*)(g_bufA + (long long)rhi * HH + col) = h;
        }
    }
}

// ---------------- CSR gather: out[i] = dinv[i]*(bufA[i] + Σ bufA[nbr]) + b ------
// 16 lanes per node, one 8B (4-half) channel chunk each.
__device__ __forceinline__ void acc_half4(float4& acc, uint2 u) {
    __half2 h0 = *(__half2*)&u.x;
    __half2 h1 = *(__half2*)&u.y;
    float2 f0 = __half22float2(h0);
    float2 f1 = __half22float2(h1);
    acc.x += f0.x; acc.y += f0.y; acc.z += f1.x; acc.w += f1.y;
}

template <bool LAST>
__global__ void k_gather(const float* __restrict__ bias) {
    int t = blockIdx.x * blockDim.x + threadIdx.x;   // NN*16 exact
    int i = t >> 4;
    int c = t & 15;
    int lane = threadIdx.x & 31;
    int sub  = lane & 15;
    unsigned mask = 0xFFFFu << (lane & 16);

    int start = g_ptr[i];
    int end   = g_ptr[i + 1];

    const uint2* __restrict__ A = (const uint2*)g_bufA;
    float4 acc = make_float4(0.f, 0.f, 0.f, 0.f);
    acc_half4(acc, A[i * 16 + c]);   // self loop

    for (int p0 = start; p0 < end; p0 += 16) {
        int myj = 0;
        if (p0 + sub < end) myj = g_csr[p0 + sub];
        int cnt = min(16, end - p0);
        if (cnt == 16) {
#pragma unroll
            for (int k = 0; k < 16; ++k) {
                int j = __shfl_sync(mask, myj, k, 16);
                acc_half4(acc, A[j * 16 + c]);
            }
        } else {
            for (int k = 0; k < cnt; ++k) {
                int j = __shfl_sync(mask, myj, k, 16);
                acc_half4(acc, A[j * 16 + c]);
            }
        }
    }

    float d = g_dinv[i];
    float4 b = ((const float4*)bias)[c];
    float4 o;
    o.x = acc.x * d + b.x;
    o.y = acc.y * d + b.y;
    o.z = acc.z * d + b.z;
    o.w = acc.w * d + b.w;
    if (LAST) {
        ((float4*)g_bufB)[i * 16 + c] = o;
    } else {
        __half2 h0 = __floats2half2_rn(o.x, o.y);
        __half2 h1 = __floats2half2_rn(o.z, o.w);
        uint2 u;
        u.x = *(unsigned int*)&h0;
        u.y = *(unsigned int*)&h1;
        ((uint2*)g_bufBh)[i * 16 + c] = u;
    }
}

// ---------------- pooling -------------------------------------------------------
__global__ void k_pool(const void* __restrict__ batch) {
    int t = blockIdx.x * blockDim.x + threadIdx.x;   // NN*16 exact
    int i = t >> 4, c = t & 15;
    int lane = threadIdx.x & 31;
    int base = lane & ~15;

    int b = 0;
    if ((lane & 15) == 0) b = load_idx(batch, i);
    b = __shfl_sync(0xffffffffu, b, base);

    float4 v = ((const float4*)g_bufB)[t];
    red_add_v4((float4*)&g_pool[b * HH + c * 4], v);
    if (c == 0) atomicAdd(&g_cnt[b], 1.0f);
}

// ---------------- head: out(G,C) = (pool/cnt) @ Wl + bl -------------------------
__global__ void k_final(const float* __restrict__ Wl, const float* __restrict__ bl,
                        float* __restrict__ out) {
    int t = blockIdx.x * blockDim.x + threadIdx.x;
    if (t >= GG * CC) return;
    int g = t / CC, c = t % CC;
    float inv = 1.0f / fmaxf(g_cnt[g], 1.0f);
    float dot = 0.0f;
#pragma unroll
    for (int h = 0; h < HH; ++h) dot += g_pool[g * HH + h] * Wl[h * CC + c];
    out[t] = dot * inv + bl[c];
}

// ---------------- launch ---------------------------------------------------------
extern "C" void kernel_launch(void* const* d_in, const int* in_sizes, int n_in,
                              void* d_out, int out_size) {
    const float* x  = (const float*)d_in[0];
    const void*  ei = d_in[1];
    const void*  bt = d_in[2];
    const float* W1 = (const float*)d_in[3];
    const float* b1 = (const float*)d_in[4];
    const float* W2 = (const float*)d_in[5];
    const float* b2 = (const float*)d_in[6];
    const float* W3 = (const float*)d_in[7];
    const float* b3 = (const float*)d_in[8];
    const float* Wl = (const float*)d_in[9];
    const float* bl = (const float*)d_in[10];
    float* out = (float*)d_out;

    const int TPB   = 256;
    const int gN    = (NN + TPB - 1) / TPB;           // 391
    const int gE    = (EE + TPB - 1) / TPB;           // 6250
    const int gNV4  = NN * 16 / TPB;                  // 6250 exact
    const int gCvt  = (NN * DD / 4 + TPB - 1) / TPB;  // 12500
    const int gGemm = (NN + 127) / 128;               // 782
    const int gZero = (GG * HH + TPB - 1) / TPB > gN ? (GG * HH + TPB - 1) / TPB : gN;

    // 0) detect index dtype; convert x to fp16
    k_detect<<<1, 256>>>((const unsigned int*)ei);
    k_cvt   <<<gCvt, TPB>>>(x);

    // 1) degrees, dinv, CSR build
    k_zero     <<<gZero, TPB>>>();
    k_deg_count<<<gE, TPB>>>(ei);
    k_scan1    <<<SCAN_BLOCKS, 256>>>();
    k_scan2    <<<1, 512>>>();
    k_scan3    <<<gN, TPB>>>();
    k_fill     <<<gE, TPB>>>(ei);

    // 2) layer 1
    k_gemm_tc<DD, true><<<gGemm, TPB>>>(W1);
    k_gather<false><<<gNV4, TPB>>>(b1);

    // 3) layer 2
    k_gemm_tc<HH, false><<<gGemm, TPB>>>(W2);
    k_gather<false><<<gNV4, TPB>>>(b2);

    // 4) layer 3
    k_gemm_tc<HH, false><<<gGemm, TPB>>>(W3);
    k_gather<true><<<gNV4, TPB>>>(b3);

    // 5) mean pool + linear head
    k_pool <<<gNV4, TPB>>>(bt);
    k_final<<<(GG * CC + TPB - 1) / TPB, TPB>>>(Wl, bl, out);
}

// round 5
// speedup vs baseline: 2.2812x; 1.0503x over previous
#include <cuda_runtime.h>
#include <cuda_fp16.h>
#include <cstdint>

// Problem constants (fixed shapes)
#define NN 100000
#define EE 1600000
#define DD 128
#define HH 64
#define CC 10
#define GG 1024
#define SCAN_BLOCKS ((NN + 255) / 256)   // 391

// ---------------- scratch (device globals; no allocations allowed) ----------
__device__ __align__(16) __half g_bufA[NN * HH]; // fp16: dinv * (X @ W)
__device__ __align__(16) __half g_bufBh[NN * HH];// fp16 layer output (GEMM input)
__device__ __align__(16) float g_dinv[NN];
__device__ __align__(16) float g_pool[GG * HH];
__device__ float g_cnt[GG];
__device__ int   g_degi[NN];
__device__ int   g_ptr[NN + 1];
__device__ int   g_cursor[NN];
__device__ int   g_bsum[512];
__device__ int   g_csr[EE];
__device__ int   g_is64;                          // 1 if indices are int64

// ---------------- helpers ----------------------------------------------------
__device__ __forceinline__ int load_idx(const void* p, long long i) {
    if (g_is64) return (int)((const long long*)p)[i];
    return ((const int*)p)[i];
}

__device__ __forceinline__ void red_add_v4(float4* addr, float4 v) {
    asm volatile("red.global.add.v4.f32 [%0], {%1,%2,%3,%4};"
                 :: "l"(addr), "f"(v.x), "f"(v.y), "f"(v.z), "f"(v.w)
                 : "memory");
}

__device__ __forceinline__ void ldsm_x4(uint32_t* r, uint32_t addr) {
    asm volatile("ldmatrix.sync.aligned.m8n8.x4.shared.b16 {%0,%1,%2,%3}, [%4];"
                 : "=r"(r[0]), "=r"(r[1]), "=r"(r[2]), "=r"(r[3]) : "r"(addr));
}

__device__ __forceinline__ void ldsm_x4_t(uint32_t* r, uint32_t addr) {
    asm volatile("ldmatrix.sync.aligned.m8n8.x4.trans.shared.b16 {%0,%1,%2,%3}, [%4];"
                 : "=r"(r[0]), "=r"(r[1]), "=r"(r[2]), "=r"(r[3]) : "r"(addr));
}

__device__ __forceinline__ void mma_16816(float* d, const uint32_t* a, const uint32_t* b) {
    asm volatile("mma.sync.aligned.m16n8k16.row.col.f32.f16.f16.f32 "
                 "{%0,%1,%2,%3}, {%4,%5,%6,%7}, {%8,%9}, {%0,%1,%2,%3};"
                 : "+f"(d[0]), "+f"(d[1]), "+f"(d[2]), "+f"(d[3])
                 : "r"(a[0]), "r"(a[1]), "r"(a[2]), "r"(a[3]), "r"(b[0]), "r"(b[1]));
}

// ---------------- dtype sniffer ----------------------------------------------
__global__ void k_detect(const unsigned int* w) {
    __shared__ unsigned int s[256];
    unsigned int acc = 0;
    const int stride = EE / (256 * 64);   // 97
    for (int j = 0; j < 64; ++j) {
        long long pair = (long long)(threadIdx.x * 64 + j) * stride;
        acc |= w[2 * pair + 1];
    }
    s[threadIdx.x] = acc;
    __syncthreads();
    for (int st = 128; st > 0; st >>= 1) {
        if (threadIdx.x < st) s[threadIdx.x] |= s[threadIdx.x + st];
        __syncthreads();
    }
    if (threadIdx.x == 0) g_is64 = (s[0] == 0u) ? 1 : 0;
}

// ---------------- degree histogram + zero-init ---------------------------------
__global__ void k_zero() {
    int i = blockIdx.x * blockDim.x + threadIdx.x;
    if (i < NN) g_degi[i] = 0;
    if (i < GG * HH) g_pool[i] = 0.0f;
    if (i < GG) g_cnt[i] = 0.0f;
}

// 4 edges per thread, vectorized index loads
__global__ void k_deg_count(const void* ei) {
    long long e0 = 4LL * (blockIdx.x * blockDim.x + threadIdx.x);
    if (e0 >= EE) return;
    int c0, c1, c2, c3;
    if (g_is64) {
        const longlong2* p = (const longlong2*)((const long long*)ei + EE + e0);
        longlong2 a = p[0], b = p[1];
        c0 = (int)a.x; c1 = (int)a.y; c2 = (int)b.x; c3 = (int)b.y;
    } else {
        int4 v = *(const int4*)((const int*)ei + EE + e0);
        c0 = v.x; c1 = v.y; c2 = v.z; c3 = v.w;
    }
    atomicAdd(&g_degi[c0], 1);
    atomicAdd(&g_degi[c1], 1);
    atomicAdd(&g_degi[c2], 1);
    atomicAdd(&g_degi[c3], 1);
}

// ---------------- scan (block-local) + dinv fused ------------------------------
__global__ void k_scan1() {
    __shared__ int s[256];
    int i = blockIdx.x * 256 + threadIdx.x;
    int v = (i < NN) ? g_degi[i] : 0;
    if (i < NN) g_dinv[i] = rsqrtf((float)(v + 1));   // +1 self loop
    s[threadIdx.x] = v;
    __syncthreads();
    for (int off = 1; off < 256; off <<= 1) {
        int add = (threadIdx.x >= off) ? s[threadIdx.x - off] : 0;
        __syncthreads();
        s[threadIdx.x] += add;
        __syncthreads();
    }
    if (i < NN) g_ptr[i] = s[threadIdx.x] - v;
    if (threadIdx.x == 255) g_bsum[blockIdx.x] = s[255];
}

__global__ void k_scan2() {    // 1 block, 512 threads
    __shared__ int s[512];
    int v = (threadIdx.x < SCAN_BLOCKS) ? g_bsum[threadIdx.x] : 0;
    s[threadIdx.x] = v;
    __syncthreads();
    for (int off = 1; off < 512; off <<= 1) {
        int add = (threadIdx.x >= off) ? s[threadIdx.x - off] : 0;
        __syncthreads();
        s[threadIdx.x] += add;
        __syncthreads();
    }
    if (threadIdx.x < SCAN_BLOCKS) g_bsum[threadIdx.x] = s[threadIdx.x] - v;
}

__global__ void k_scan3() {
    int i = blockIdx.x * blockDim.x + threadIdx.x;
    if (i < NN) {
        int p = g_ptr[i] + g_bsum[i >> 8];
        g_ptr[i] = p;
        g_cursor[i] = p;
    }
    if (i == 0) g_ptr[NN] = EE;
}

// ---------------- CSR fill: bucket rows by col (4 edges/thread) -----------------
__global__ void k_fill(const void* __restrict__ ei) {
    long long e0 = 4LL * (blockIdx.x * blockDim.x + threadIdx.x);
    if (e0 >= EE) return;
    int r0, r1, r2, r3, c0, c1, c2, c3;
    if (g_is64) {
        const longlong2* pr = (const longlong2*)((const long long*)ei + e0);
        const longlong2* pc = (const longlong2*)((const long long*)ei + EE + e0);
        longlong2 ra = pr[0], rb = pr[1], ca = pc[0], cb = pc[1];
        r0 = (int)ra.x; r1 = (int)ra.y; r2 = (int)rb.x; r3 = (int)rb.y;
        c0 = (int)ca.x; c1 = (int)ca.y; c2 = (int)cb.x; c3 = (int)cb.y;
    } else {
        int4 rv = *(const int4*)((const int*)ei + e0);
        int4 cv = *(const int4*)((const int*)ei + EE + e0);
        r0 = rv.x; r1 = rv.y; r2 = rv.z; r3 = rv.w;
        c0 = cv.x; c1 = cv.y; c2 = cv.z; c3 = cv.w;
    }
    g_csr[atomicAdd(&g_cursor[c0], 1)] = r0;
    g_csr[atomicAdd(&g_cursor[c1], 1)] = r1;
    g_csr[atomicAdd(&g_cursor[c2], 1)] = r2;
    g_csr[atomicAdd(&g_cursor[c3], 1)] = r3;
}

// ---------------- tensor-core GEMM: bufA = fp16(dinv ⊙ (X(N,K) @ W(K,64))) -----
// 256 threads / 8 warps, block tile 128 rows x 64 cols, K chunked by 64.
// FIRST: X fp32 from global (converted in smem load); else fp16 g_bufBh.
template <int K, bool FIRST>
__global__ void k_gemm_tc(const float* __restrict__ W, const float* __restrict__ Xf) {
    constexpr int LDX = 72;   // 64 + 8 halfs pad
    __shared__ __half sX[128 * LDX];
    __shared__ __half sW[64 * LDX];

    const int tid  = threadIdx.x;
    const int wid  = tid >> 5;
    const int lane = tid & 31;
    const int row0 = blockIdx.x * 128;
    const int wr0  = wid * 16;          // warp row offset within tile

    float acc[8][4];
#pragma unroll
    for (int n = 0; n < 8; ++n)
#pragma unroll
        for (int i = 0; i < 4; ++i) acc[n][i] = 0.0f;

    const uint32_t sX_base = (uint32_t)__cvta_generic_to_shared(sX);
    const uint32_t sW_base = (uint32_t)__cvta_generic_to_shared(sW);

    for (int kt = 0; kt < K; kt += 64) {
        if (FIRST) {
            // fp32 global -> fp16 smem: 128 rows x 64 floats = 2048 float4
#pragma unroll
            for (int it = 0; it < 8; ++it) {
                int idx = it * 256 + tid;        // 0..2047
                int r = idx >> 4, f4 = idx & 15;
                int grow = row0 + r;
                float4 v = make_float4(0.f, 0.f, 0.f, 0.f);
                if (grow < NN) v = *(const float4*)(Xf + (long long)grow * K + kt + f4 * 4);
                __half2 h0 = __floats2half2_rn(v.x, v.y);
                __half2 h1 = __floats2half2_rn(v.z, v.w);
                uint2 u;
                u.x = *(unsigned int*)&h0;
                u.y = *(unsigned int*)&h1;
                *(uint2*)(sX + r * LDX + f4 * 4) = u;
            }
        } else {
            // fp16 global -> smem: 128 rows x 64 halfs = 1024 uint4
#pragma unroll
            for (int it = 0; it < 4; ++it) {
                int idx = it * 256 + tid;        // 0..1023
                int r = idx >> 3, ch = idx & 7;
                int grow = row0 + r;
                uint4 u = make_uint4(0, 0, 0, 0);
                if (grow < NN) u = *(const uint4*)(g_bufBh + (long long)grow * K + kt + ch * 8);
                *(uint4*)(sX + r * LDX + ch * 8) = u;
            }
        }
        // load + convert W tile: 64 x 64
#pragma unroll
        for (int it = 0; it < 16; ++it) {
            int idx = it * 256 + tid;            // 0..4095
            int k = idx >> 6, n = idx & 63;
            sW[k * LDX + n] = __float2half(W[(kt + k) * HH + n]);
        }
        __syncthreads();

#pragma unroll
        for (int ks = 0; ks < 64; ks += 16) {
            uint32_t a[4];
            {
                int r = wr0 + (lane & 15);
                int kk = ks + ((lane >> 4) * 8);
                ldsm_x4(a, sX_base + (r * LDX + kk) * 2);
            }
#pragma unroll
            for (int np = 0; np < 4; ++np) {     // n-pairs: (np*16, np*16+8)
                uint32_t b[4];
                int krow = ks + (lane & 7) + (((lane >> 3) & 1) * 8);
                int ncol = np * 16 + ((lane >> 4) * 8);
                ldsm_x4_t(b, sW_base + (krow * LDX + ncol) * 2);
                mma_16816(acc[np * 2 + 0], a, b + 0);
                mma_16816(acc[np * 2 + 1], a, b + 2);
            }
        }
        __syncthreads();
    }

    // epilogue: scale by dinv, store fp16 to g_bufA
    const int rlo = row0 + wr0 + (lane >> 2);
    const int rhi = rlo + 8;
    const int cb  = (lane & 3) * 2;
    float dlo = (rlo < NN) ? g_dinv[rlo] : 0.0f;
    float dhi = (rhi < NN) ? g_dinv[rhi] : 0.0f;
#pragma unroll
    for (int nt = 0; nt < 8; ++nt) {
        int col = nt * 8 + cb;
        if (rlo < NN) {
            __half2 h = __floats2half2_rn(acc[nt][0] * dlo, acc[nt][1] * dlo);
            *(__half2*)(g_bufA + (long long)rlo * HH + col) = h;
        }
        if (rhi < NN) {
            __half2 h = __floats2half2_rn(acc[nt][2] * dhi, acc[nt][3] * dhi);
            *(__half2*)(g_bufA + (long long)rhi * HH + col) = h;
        }
    }
}

// ---------------- CSR gather ------------------------------------------------------
// 16 lanes per node, one 8B (4-half) channel chunk each.
// !LAST: bufBh[i] = fp16(dinv[i]*(bufA[i] + Σ bufA[nbr]) + bias)
//  LAST: RED dinv[i]*(bufA[i] + Σ bufA[nbr]) into g_pool[batch[i]] (+ cnt)
__device__ __forceinline__ void acc_half4(float4& acc, uint2 u) {
    __half2 h0 = *(__half2*)&u.x;
    __half2 h1 = *(__half2*)&u.y;
    float2 f0 = __half22float2(h0);
    float2 f1 = __half22float2(h1);
    acc.x += f0.x; acc.y += f0.y; acc.z += f1.x; acc.w += f1.y;
}

template <bool LAST>
__global__ void k_gather(const float* __restrict__ bias, const void* __restrict__ batch) {
    int t = blockIdx.x * blockDim.x + threadIdx.x;   // NN*16 exact
    int i = t >> 4;
    int c = t & 15;
    int lane = threadIdx.x & 31;
    int sub  = lane & 15;
    int base = lane & ~15;
    unsigned mask = 0xFFFFu << (lane & 16);

    int start = g_ptr[i];
    int end   = g_ptr[i + 1];

    const uint2* __restrict__ A = (const uint2*)g_bufA;
    float4 acc = make_float4(0.f, 0.f, 0.f, 0.f);
    acc_half4(acc, A[i * 16 + c]);   // self loop

    for (int p0 = start; p0 < end; p0 += 16) {
        int myj = 0;
        if (p0 + sub < end) myj = g_csr[p0 + sub];
        int cnt = min(16, end - p0);
        if (cnt == 16) {
#pragma unroll
            for (int k = 0; k < 16; ++k) {
                int j = __shfl_sync(mask, myj, k, 16);
                acc_half4(acc, A[j * 16 + c]);
            }
        } else {
            for (int k = 0; k < cnt; ++k) {
                int j = __shfl_sync(mask, myj, k, 16);
                acc_half4(acc, A[j * 16 + c]);
            }
        }
    }

    float d = g_dinv[i];
    if (LAST) {
        float4 o;
        o.x = acc.x * d; o.y = acc.y * d; o.z = acc.z * d; o.w = acc.w * d;
        int b = 0;
        if (sub == 0) b = load_idx(batch, i);
        b = __shfl_sync(0xffffffffu, b, base);
        red_add_v4((float4*)&g_pool[b * HH + c * 4], o);
        if (c == 0) atomicAdd(&g_cnt[b], 1.0f);
    } else {
        float4 bv = ((const float4*)bias)[c];
        __half2 h0 = __floats2half2_rn(acc.x * d + bv.x, acc.y * d + bv.y);
        __half2 h1 = __floats2half2_rn(acc.z * d + bv.z, acc.w * d + bv.w);
        uint2 u;
        u.x = *(unsigned int*)&h0;
        u.y = *(unsigned int*)&h1;
        ((uint2*)g_bufBh)[i * 16 + c] = u;
    }
}

// ---------------- head: out(G,C) = (pool/cnt + b3) @ Wl + bl --------------------
__global__ void k_final(const float* __restrict__ Wl, const float* __restrict__ bl,
                        const float* __restrict__ b3, float* __restrict__ out) {
    int t = blockIdx.x * blockDim.x + threadIdx.x;
    if (t >= GG * CC) return;
    int g = t / CC, c = t % CC;
    float cnt = g_cnt[g];
    float inv = (cnt > 0.0f) ? (1.0f / cnt) : 0.0f;
    float sel = (cnt > 0.0f) ? 1.0f : 0.0f;
    float dot = 0.0f;
#pragma unroll
    for (int h = 0; h < HH; ++h)
        dot += (g_pool[g * HH + h] * inv + b3[h] * sel) * Wl[h * CC + c];
    out[t] = dot + bl[c];
}

// ---------------- launch ---------------------------------------------------------
extern "C" void kernel_launch(void* const* d_in, const int* in_sizes, int n_in,
                              void* d_out, int out_size) {
    const float* x  = (const float*)d_in[0];
    const void*  ei = d_in[1];
    const void*  bt = d_in[2];
    const float* W1 = (const float*)d_in[3];
    const float* b1 = (const float*)d_in[4];
    const float* W2 = (const float*)d_in[5];
    const float* b2 = (const float*)d_in[6];
    const float* W3 = (const float*)d_in[7];
    const float* b3 = (const float*)d_in[8];
    const float* Wl = (const float*)d_in[9];
    const float* bl = (const float*)d_in[10];
    float* out = (float*)d_out;

    const int TPB   = 256;
    const int gN    = (NN + TPB - 1) / TPB;           // 391
    const int gE4   = (EE / 4 + TPB - 1) / TPB;       // 1563
    const int gNV4  = NN * 16 / TPB;                  // 6250 exact
    const int gGemm = (NN + 127) / 128;               // 782
    const int gZero = (GG * HH + TPB - 1) / TPB > gN ? (GG * HH + TPB - 1) / TPB : gN;

    // 0) detect index dtype
    k_detect<<<1, 256>>>((const unsigned int*)ei);

    // 1) degrees, dinv, CSR build
    k_zero     <<<gZero, TPB>>>();
    k_deg_count<<<gE4, TPB>>>(ei);
    k_scan1    <<<SCAN_BLOCKS, 256>>>();
    k_scan2    <<<1, 512>>>();
    k_scan3    <<<gN, TPB>>>();
    k_fill     <<<gE4, TPB>>>(ei);

    // 2) layer 1 (reads fp32 x directly)
    k_gemm_tc<DD, true><<<gGemm, TPB>>>(W1, x);
    k_gather<false><<<gNV4, TPB>>>(b1, nullptr);

    // 3) layer 2
    k_gemm_tc<HH, false><<<gGemm, TPB>>>(W2, nullptr);
    k_gather<false><<<gNV4, TPB>>>(b2, nullptr);

    // 4) layer 3 (gather fused with mean-pool accumulation)
    k_gemm_tc<HH, false><<<gGemm, TPB>>>(W3, nullptr);
    k_gather<true><<<gNV4, TPB>>>(nullptr, bt);

    // 5) linear head (b3 folded in)
    k_final<<<(GG * CC + TPB - 1) / TPB, TPB>>>(Wl, bl, b3, out);
}